// round 16
// baseline (speedup 1.0000x reference)
#include <cuda_runtime.h>
#include <math.h>

#define F 64
#define KSEL 256
#define NMAX 20000
#define EMAX 320000
#define ETMAX (NMAX + EMAX)
#define NEG_INF (-3.402823466e38f)
#define XS 68

// ---------------- scratch (static __device__, zero-initialized) ----------------
__device__ float g_h[NMAX * F];
__device__ float g_x1[NMAX * F];
__device__ float g_x2[NMAX * F];
__device__ float g_xc[NMAX * F];
__device__ float g_dis[NMAX];
__device__ float g_pa[NMAX];
__device__ float g_av[NMAX], g_bv[NMAX], g_cv[NMAX], g_fit[NMAX];
__device__ float g_score[ETMAX];
__device__ int   g_rowS[ETMAX];
__device__ int   g_epos[EMAX];
__device__ int   g_cnt[NMAX], g_ptr[NMAX + 1];
__device__ unsigned long long g_cand[16 * 256];
__device__ int   g_perm[KSEL];
__device__ float g_fitk[KSEL];
__device__ int   g_entR[ETMAX], g_entK[ETMAX];
__device__ float g_entV[ETMAX];
__device__ int   g_nent;
__device__ float g_vq[F + 1];
__device__ float g_AS[(size_t)NMAX * KSEL];

// ---------------- helpers ----------------
__device__ __forceinline__ float wredsum(float v) {
    #pragma unroll
    for (int d = 16; d; d >>= 1) v += __shfl_xor_sync(0xFFFFFFFFu, v, d);
    return v;
}
__device__ __forceinline__ float wredmax(float v) {
    #pragma unroll
    for (int d = 16; d; d >>= 1) v = fmaxf(v, __shfl_xor_sync(0xFFFFFFFFu, v, d));
    return v;
}
__device__ __forceinline__ unsigned long long make_key(float f, int i) {
    unsigned u = __float_as_uint(f);
    u = (u & 0x80000000u) ? ~u : (u | 0x80000000u);
    return ((unsigned long long)u << 32) | (unsigned)(0xFFFFFFFFu - (unsigned)i);
}
template <int NSORT>
__device__ void bitonic_desc(unsigned long long* s) {
    int t = threadIdx.x;
    for (int k = 2; k <= NSORT; k <<= 1) {
        for (int j = k >> 1; j > 0; j >>= 1) {
            for (int i = t; i < NSORT; i += blockDim.x) {
                int ixj = i ^ j;
                if (ixj > i) {
                    unsigned long long a = s[i], b = s[ixj];
                    bool sw = ((i & k) == 0) ? (a < b) : (a > b);
                    if (sw) { s[i] = b; s[ixj] = a; }
                }
            }
            __syncthreads();
        }
    }
}

// ---------------- zeroing kernel (side stream; replaces memset nodes) --------
__global__ void k_zero(int Nn, float* __restrict__ outA) {
    int gtid = blockIdx.x * blockDim.x + threadIdx.x;
    int gsz = gridDim.x * blockDim.x;
    float4 z4 = make_float4(0.f, 0.f, 0.f, 0.f);
    size_t nAS4 = ((size_t)Nn * KSEL) >> 2;
    float4* AS4 = (float4*)g_AS;
    for (size_t i = gtid; i < nAS4; i += gsz) AS4[i] = z4;
    float4* outA4 = (float4*)outA;
    for (int i = gtid; i < (KSEL * KSEL) / 4; i += gsz) outA4[i] = z4;
}

// ---------------- CSR build (computes vq, resets g_nent) ----------------------
__global__ void k_count(const int* __restrict__ ei, int E,
                        const float* __restrict__ linW, const float* __restrict__ linb,
                        const float* __restrict__ attW) {
    int e = blockIdx.x * blockDim.x + threadIdx.x;
    if (blockIdx.x == 0) {
        int t = threadIdx.x;
        if (t < F) {
            float s = 0.f;
            #pragma unroll 8
            for (int c = 0; c < F; c++) s += linW[t * F + c] * attW[c];
            g_vq[t] = s;
        } else if (t == F) {
            float s = 0.f;
            for (int c = 0; c < F; c++) s += linb[c] * attW[c];
            g_vq[F] = s;
        } else if (t == F + 1) {
            g_nent = 0;
        }
    }
    if (e >= E) return;
    int c = ei[E + e];
    g_epos[e] = atomicAdd(&g_cnt[c], 1);
}

__global__ void __launch_bounds__(1024) k_scan(int Nn) {
    __shared__ int warpsum[32];
    int t = threadIdx.x, lane = t & 31, wid = t >> 5;
    int offset = 0;
    for (int base = 0; base < Nn; base += 1024) {
        int i = base + t;
        int v = 0;
        if (i < Nn) { v = g_cnt[i] + 1; g_cnt[i] = 0; }
        int x = v;
        #pragma unroll
        for (int d = 1; d < 32; d <<= 1) {
            int y = __shfl_up_sync(0xFFFFFFFFu, x, d);
            if (lane >= d) x += y;
        }
        if (lane == 31) warpsum[wid] = x;
        __syncthreads();
        if (wid == 0) {
            int s = warpsum[lane];
            #pragma unroll
            for (int d = 1; d < 32; d <<= 1) {
                int y = __shfl_up_sync(0xFFFFFFFFu, s, d);
                if (lane >= d) s += y;
            }
            warpsum[lane] = s;
        }
        __syncthreads();
        int ex = x - v + (wid > 0 ? warpsum[wid - 1] : 0);
        int val = offset + ex;
        if (i < Nn) {
            g_ptr[i] = val;
            g_dis[i] = rsqrtf((float)v);
        }
        offset += warpsum[31];
        __syncthreads();
    }
    if (t == 0) g_ptr[Nn] = offset;
}

__global__ void k_scatter(const int* __restrict__ ei, int E, int Nn) {
    int e = blockIdx.x * blockDim.x + threadIdx.x;
    int Et = E + Nn;
    if (e >= Et) return;
    if (e < E) {
        int c = ei[E + e];
        g_rowS[g_ptr[c] + g_epos[e]] = ei[e];
    } else {
        int c = e - E;
        g_rowS[g_ptr[c + 1] - 1] = c;
    }
}

// ---------------- dense matmul ----------------
__global__ void __launch_bounds__(256) k_matmul(const float* __restrict__ X,
                                                const float* __restrict__ W,
                                                float* __restrict__ Y, int n) {
    __shared__ float Ws[F * F];
    __shared__ float Xs[64 * XS];
    int t = threadIdx.x;
    const float4* W4 = (const float4*)W;
    float4* Ws4 = (float4*)Ws;
    #pragma unroll
    for (int i = 0; i < 4; i++) Ws4[t + 256 * i] = W4[t + 256 * i];

    int r0 = blockIdx.x * 64;
    int rows = n - r0; if (rows > 64) rows = 64;
    const float4* X4 = (const float4*)(X + (size_t)r0 * F);
    for (int i = t; i < 64 * 16; i += 256) {
        int row = i >> 4, c4 = i & 15;
        float4 v = (row < rows) ? X4[row * 16 + c4] : make_float4(0.f, 0.f, 0.f, 0.f);
        *(float4*)(Xs + row * XS + c4 * 4) = v;
    }
    __syncthreads();

    int tx = t & 15, ty = t >> 4;
    float4 a0 = make_float4(0.f,0.f,0.f,0.f), a1 = a0, a2 = a0, a3 = a0;
    const float* xr0 = Xs + (ty * 4 + 0) * XS;
    const float* xr1 = Xs + (ty * 4 + 1) * XS;
    const float* xr2 = Xs + (ty * 4 + 2) * XS;
    const float* xr3 = Xs + (ty * 4 + 3) * XS;
    #pragma unroll
    for (int k0 = 0; k0 < F; k0 += 4) {
        float4 xv0 = *(const float4*)(xr0 + k0);
        float4 xv1 = *(const float4*)(xr1 + k0);
        float4 xv2 = *(const float4*)(xr2 + k0);
        float4 xv3 = *(const float4*)(xr3 + k0);
        #pragma unroll
        for (int kk = 0; kk < 4; kk++) {
            float4 wv = *(const float4*)(Ws + (k0 + kk) * F + tx * 4);
            float x0 = (&xv0.x)[kk], x1 = (&xv1.x)[kk];
            float x2 = (&xv2.x)[kk], x3 = (&xv3.x)[kk];
            a0.x += x0 * wv.x; a0.y += x0 * wv.y; a0.z += x0 * wv.z; a0.w += x0 * wv.w;
            a1.x += x1 * wv.x; a1.y += x1 * wv.y; a1.z += x1 * wv.z; a1.w += x1 * wv.w;
            a2.x += x2 * wv.x; a2.y += x2 * wv.y; a2.z += x2 * wv.z; a2.w += x2 * wv.w;
            a3.x += x3 * wv.x; a3.y += x3 * wv.y; a3.z += x3 * wv.z; a3.w += x3 * wv.w;
        }
    }
    int rb = r0 + ty * 4;
    if (rb + 0 < n) ((float4*)(Y + (size_t)(rb + 0) * F))[tx] = a0;
    if (rb + 1 < n) ((float4*)(Y + (size_t)(rb + 1) * F))[tx] = a1;
    if (rb + 2 < n) ((float4*)(Y + (size_t)(rb + 2) * F))[tx] = a2;
    if (rb + 3 < n) ((float4*)(Y + (size_t)(rb + 3) * F))[tx] = a3;
}

// ---------------- segment gathers ----------------
template <bool WITH_PA>
__global__ void k_gcnagg(const float* __restrict__ h, const float* __restrict__ b,
                         const float* __restrict__ attW, float* __restrict__ out, int n) {
    int w = (blockIdx.x * blockDim.x + threadIdx.x) >> 5;
    int l = threadIdx.x & 31;
    if (w >= n) return;
    int half = l >> 4, f4 = l & 15;
    int s = g_ptr[w], e = g_ptr[w + 1];
    float dc = g_dis[w];
    float4 a0 = make_float4(0.f, 0.f, 0.f, 0.f);
    float4 a1 = make_float4(0.f, 0.f, 0.f, 0.f);
    int p = s + half;
    for (; p + 2 < e; p += 4) {
        int r0 = g_rowS[p], r1 = g_rowS[p + 2];
        float n0 = dc * g_dis[r0], n1 = dc * g_dis[r1];
        float4 h0 = *(const float4*)(h + r0 * F + f4 * 4);
        float4 h1 = *(const float4*)(h + r1 * F + f4 * 4);
        a0.x += n0 * h0.x; a0.y += n0 * h0.y; a0.z += n0 * h0.z; a0.w += n0 * h0.w;
        a1.x += n1 * h1.x; a1.y += n1 * h1.y; a1.z += n1 * h1.z; a1.w += n1 * h1.w;
    }
    if (p < e) {
        int r0 = g_rowS[p];
        float n0 = dc * g_dis[r0];
        float4 h0 = *(const float4*)(h + r0 * F + f4 * 4);
        a0.x += n0 * h0.x; a0.y += n0 * h0.y; a0.z += n0 * h0.z; a0.w += n0 * h0.w;
    }
    a0.x += a1.x; a0.y += a1.y; a0.z += a1.z; a0.w += a1.w;
    a0.x += __shfl_xor_sync(0xFFFFFFFFu, a0.x, 16);
    a0.y += __shfl_xor_sync(0xFFFFFFFFu, a0.y, 16);
    a0.z += __shfl_xor_sync(0xFFFFFFFFu, a0.z, 16);
    a0.w += __shfl_xor_sync(0xFFFFFFFFu, a0.w, 16);
    float4 bb = *(const float4*)(b + f4 * 4);
    a0.x = fmaxf(a0.x + bb.x, 0.f);
    a0.y = fmaxf(a0.y + bb.y, 0.f);
    a0.z = fmaxf(a0.z + bb.z, 0.f);
    a0.w = fmaxf(a0.w + bb.w, 0.f);
    if (half == 0) *(float4*)(out + w * F + f4 * 4) = a0;
    if (WITH_PA) {
        float part = 0.f;
        if (half == 0) {
            float4 aw = *(const float4*)(attW + F + f4 * 4);
            part = a0.x * aw.x + a0.y * aw.y + a0.z * aw.z + a0.w * aw.w;
        }
        part = wredsum(part);
        if (l == 0) g_pa[w] = part;
    }
}

// fused: segmax over x2 -> qa in registers -> leaky score -> softmax
__global__ void k_attn(const float* __restrict__ x2, const float* __restrict__ attb, int n) {
    int w = (blockIdx.x * blockDim.x + threadIdx.x) >> 5;
    int l = threadIdx.x & 31;
    if (w >= n) return;
    int half = l >> 4, f4 = l & 15;
    int s = g_ptr[w], e = g_ptr[w + 1];
    float4 a0 = make_float4(NEG_INF, NEG_INF, NEG_INF, NEG_INF);
    float4 a1 = make_float4(NEG_INF, NEG_INF, NEG_INF, NEG_INF);
    int p = s + half;
    for (; p + 2 < e; p += 4) {
        int r0 = g_rowS[p], r1 = g_rowS[p + 2];
        float4 h0 = *(const float4*)(x2 + r0 * F + f4 * 4);
        float4 h1 = *(const float4*)(x2 + r1 * F + f4 * 4);
        a0.x = fmaxf(a0.x, h0.x); a0.y = fmaxf(a0.y, h0.y);
        a0.z = fmaxf(a0.z, h0.z); a0.w = fmaxf(a0.w, h0.w);
        a1.x = fmaxf(a1.x, h1.x); a1.y = fmaxf(a1.y, h1.y);
        a1.z = fmaxf(a1.z, h1.z); a1.w = fmaxf(a1.w, h1.w);
    }
    if (p < e) {
        int r0 = g_rowS[p];
        float4 h0 = *(const float4*)(x2 + r0 * F + f4 * 4);
        a0.x = fmaxf(a0.x, h0.x); a0.y = fmaxf(a0.y, h0.y);
        a0.z = fmaxf(a0.z, h0.z); a0.w = fmaxf(a0.w, h0.w);
    }
    a0.x = fmaxf(a0.x, a1.x); a0.y = fmaxf(a0.y, a1.y);
    a0.z = fmaxf(a0.z, a1.z); a0.w = fmaxf(a0.w, a1.w);
    a0.x = fmaxf(a0.x, __shfl_xor_sync(0xFFFFFFFFu, a0.x, 16));
    a0.y = fmaxf(a0.y, __shfl_xor_sync(0xFFFFFFFFu, a0.y, 16));
    a0.z = fmaxf(a0.z, __shfl_xor_sync(0xFFFFFFFFu, a0.z, 16));
    a0.w = fmaxf(a0.w, __shfl_xor_sync(0xFFFFFFFFu, a0.w, 16));
    float part = 0.f;
    if (half == 0) {
        float4 vv = *(const float4*)(g_vq + f4 * 4);
        part = a0.x * vv.x + a0.y * vv.y + a0.z * vv.z + a0.w * vv.w;
    }
    part = wredsum(part);
    float qb = part + g_vq[F] + attb[0];
    int deg = e - s;
    if (deg <= 32) {
        int q = s + l;
        bool act = q < e;
        float sc = NEG_INF;
        if (act) {
            sc = qb + g_pa[g_rowS[q]];
            sc = (sc >= 0.f) ? sc : 0.2f * sc;
        }
        float m = wredmax(sc);
        float ex = act ? expf(sc - m) : 0.f;
        float sum = wredsum(ex);
        if (act) g_score[q] = ex / sum;
    } else {
        float m = NEG_INF;
        for (int q = s + l; q < e; q += 32) {
            float sc = qb + g_pa[g_rowS[q]];
            sc = (sc >= 0.f) ? sc : 0.2f * sc;
            g_score[q] = sc;
            m = fmaxf(m, sc);
        }
        m = wredmax(m);
        float sum = 0.f;
        for (int q = s + l; q < e; q += 32) sum += expf(g_score[q] - m);
        sum = wredsum(sum);
        float invs = 1.f / sum;
        for (int q = s + l; q < e; q += 32) g_score[q] = expf(g_score[q] - m) * invs;
    }
}

// xc = sum score * x2[row], fused le dots epilogue
__global__ void k_xc(const float* __restrict__ le1W, const float* __restrict__ le1b,
                     const float* __restrict__ le2W, const float* __restrict__ le3W, int n) {
    int w = (blockIdx.x * blockDim.x + threadIdx.x) >> 5;
    int l = threadIdx.x & 31;
    if (w >= n) return;
    int half = l >> 4, f4 = l & 15;
    int s = g_ptr[w], e = g_ptr[w + 1];
    float4 a0 = make_float4(0.f, 0.f, 0.f, 0.f);
    float4 a1 = make_float4(0.f, 0.f, 0.f, 0.f);
    int p = s + half;
    for (; p + 2 < e; p += 4) {
        int r0 = g_rowS[p], r1 = g_rowS[p + 2];
        float s0 = g_score[p], s1 = g_score[p + 2];
        float4 h0 = *(const float4*)(g_x2 + r0 * F + f4 * 4);
        float4 h1 = *(const float4*)(g_x2 + r1 * F + f4 * 4);
        a0.x += s0 * h0.x; a0.y += s0 * h0.y; a0.z += s0 * h0.z; a0.w += s0 * h0.w;
        a1.x += s1 * h1.x; a1.y += s1 * h1.y; a1.z += s1 * h1.z; a1.w += s1 * h1.w;
    }
    if (p < e) {
        int r0 = g_rowS[p];
        float s0 = g_score[p];
        float4 h0 = *(const float4*)(g_x2 + r0 * F + f4 * 4);
        a0.x += s0 * h0.x; a0.y += s0 * h0.y; a0.z += s0 * h0.z; a0.w += s0 * h0.w;
    }
    a0.x += a1.x; a0.y += a1.y; a0.z += a1.z; a0.w += a1.w;
    a0.x += __shfl_xor_sync(0xFFFFFFFFu, a0.x, 16);
    a0.y += __shfl_xor_sync(0xFFFFFFFFu, a0.y, 16);
    a0.z += __shfl_xor_sync(0xFFFFFFFFu, a0.z, 16);
    a0.w += __shfl_xor_sync(0xFFFFFFFFu, a0.w, 16);
    float s1 = 0.f, s2 = 0.f, s3 = 0.f;
    if (half == 0) {
        *(float4*)(g_xc + w * F + f4 * 4) = a0;
        float4 w1 = *(const float4*)(le1W + f4 * 4);
        float4 w2 = *(const float4*)(le2W + f4 * 4);
        float4 w3 = *(const float4*)(le3W + f4 * 4);
        s1 = a0.x * w1.x + a0.y * w1.y + a0.z * w1.z + a0.w * w1.w;
        s2 = a0.x * w2.x + a0.y * w2.y + a0.z * w2.z + a0.w * w2.w;
        s3 = a0.x * w3.x + a0.y * w3.y + a0.z * w3.z + a0.w * w3.w;
    }
    s1 = wredsum(s1); s2 = wredsum(s2); s3 = wredsum(s3);
    if (l == 0) { g_av[w] = s1 + le1b[0]; g_bv[w] = s2; g_cv[w] = s3; }
}

__global__ void k_fitness(const float* __restrict__ le3b, int n) {
    int w = (blockIdx.x * blockDim.x + threadIdx.x) >> 5;
    int l = threadIdx.x & 31;
    if (w >= n) return;
    int s = g_ptr[w], e = g_ptr[w + 1];
    float sum = 0.f;
    for (int p = s + l; p < e; p += 32) sum += g_av[g_rowS[p]];
    sum = wredsum(sum);
    if (l == 0) {
        float deg = (float)(e - s);
        float val = sum - deg * g_bv[w] + g_cv[w] + le3b[0];
        g_fit[w] = 1.f / (1.f + expf(-val));
    }
}

// ---------------- exact top-K (jax semantics) ----------------
__global__ void __launch_bounds__(1024) k_topk1(int n) {
    __shared__ unsigned long long s[2048];
    int t = threadIdx.x;
    int base = blockIdx.x * 2048;
    for (int j = t; j < 2048; j += 1024) {
        int i = base + j;
        s[j] = (i < n) ? make_key(g_fit[i], i) : 0ULL;
    }
    __syncthreads();
    bitonic_desc<2048>(s);
    if (t < 256) g_cand[blockIdx.x * 256 + t] = s[t];
}

__global__ void __launch_bounds__(1024) k_topk2(int n2) {
    __shared__ unsigned long long s[4096];
    int t = threadIdx.x;
    for (int j = t; j < 4096; j += 1024) s[j] = (j < n2) ? g_cand[j] : 0ULL;
    __syncthreads();
    bitonic_desc<4096>(s);
    if (t < KSEL) {
        unsigned long long key = s[t];
        int idx = (int)(0xFFFFFFFFu - (unsigned)(key & 0xFFFFFFFFu));
        g_perm[t] = idx;
        g_fitk[t] = g_fit[idx];
    }
}

// ---------------- sparse S entries + AS scatter (perm-driven, warp per k) ----
__global__ void k_entries() {
    int k = (blockIdx.x * blockDim.x + threadIdx.x) >> 5;
    int l = threadIdx.x & 31;
    if (k >= KSEL) return;
    int node = g_perm[k];
    int s = g_ptr[node], e = g_ptr[node + 1];
    for (int p = s + l; p < e; p += 32) {
        int r = g_rowS[p];
        float val = g_score[p];
        int idx = atomicAdd(&g_nent, 1);
        g_entR[idx] = r;
        g_entK[idx] = k;
        g_entV[idx] = val;
        int s2 = g_ptr[r], e2 = g_ptr[r + 1];
        for (int q = s2; q < e2; q++)
            atomicAdd(&g_AS[(size_t)g_rowS[q] * KSEL + k], val);
    }
}

// A_new (skipping diagonal contributions) fused with final outputs.
__global__ void k_Anew_final(float* __restrict__ out) {
    float* outA = out + KSEL * F;
    int gtid = blockIdx.x * blockDim.x + threadIdx.x;
    int gsz = gridDim.x * blockDim.x;
    int w = gtid >> 5;
    int l = threadIdx.x & 31;
    int nw = gsz >> 5;
    int ne = g_nent;
    for (int i = w; i < ne; i += nw) {
        int r = g_entR[i];
        int k1 = g_entK[i];
        float v = g_entV[i];
        const float4* asr = (const float4*)(g_AS + (size_t)r * KSEL);
        float4 x0 = asr[l * 2], x1 = asr[l * 2 + 1];
        float* dst = outA + k1 * KSEL + l * 8;
        int c0 = l * 8;
        if (c0 + 0 != k1) atomicAdd(dst + 0, v * x0.x);
        if (c0 + 1 != k1) atomicAdd(dst + 1, v * x0.y);
        if (c0 + 2 != k1) atomicAdd(dst + 2, v * x0.z);
        if (c0 + 3 != k1) atomicAdd(dst + 3, v * x0.w);
        if (c0 + 4 != k1) atomicAdd(dst + 4, v * x1.x);
        if (c0 + 5 != k1) atomicAdd(dst + 5, v * x1.y);
        if (c0 + 6 != k1) atomicAdd(dst + 6, v * x1.z);
        if (c0 + 7 != k1) atomicAdd(dst + 7, v * x1.w);
    }
    for (int i = gtid; i < KSEL * F; i += gsz) {
        int k = i >> 6, f = i & 63;
        out[i] = g_xc[g_perm[k] * F + f] * g_fitk[k];
    }
    for (int i = gtid; i < KSEL; i += gsz) {
        out[KSEL * F + KSEL * KSEL + i] = (float)g_perm[i];
        out[KSEL * F + i * KSEL + i] = 1.0f;
    }
}

// ---------------- launch ----------------
extern "C" void kernel_launch(void* const* d_in, const int* in_sizes, int n_in,
                              void* d_out, int out_size) {
    const float* x     = (const float*)d_in[0];
    const int*   ei    = (const int*)d_in[1];
    const float* W0    = (const float*)d_in[2];
    const float* b0    = (const float*)d_in[3];
    const float* W1    = (const float*)d_in[4];
    const float* b1    = (const float*)d_in[5];
    const float* linW  = (const float*)d_in[6];
    const float* linb  = (const float*)d_in[7];
    const float* attW  = (const float*)d_in[8];
    const float* attb  = (const float*)d_in[9];
    const float* le1W  = (const float*)d_in[10];
    const float* le1b  = (const float*)d_in[11];
    const float* le2W  = (const float*)d_in[12];
    const float* le3W  = (const float*)d_in[13];
    const float* le3b  = (const float*)d_in[14];
    float* out = (float*)d_out;

    int N  = in_sizes[0] / F;
    int E  = in_sizes[1] / 2;
    int Et = E + N;

    void* vp;
    cudaGetSymbolAddress(&vp, g_h);   float* p_h  = (float*)vp;
    cudaGetSymbolAddress(&vp, g_x1);  float* p_x1 = (float*)vp;
    cudaGetSymbolAddress(&vp, g_x2);  float* p_x2 = (float*)vp;

    static cudaStream_t s1 = nullptr;
    static cudaEvent_t evFork = nullptr, evJoin = nullptr, evZero = nullptr;
    if (!s1) {
        cudaStreamCreateWithFlags(&s1, cudaStreamNonBlocking);
        cudaEventCreateWithFlags(&evFork, cudaEventDisableTiming);
        cudaEventCreateWithFlags(&evJoin, cudaEventDisableTiming);
        cudaEventCreateWithFlags(&evZero, cudaEventDisableTiming);
    }

    int eB  = (E + 255) / 256;
    int tEB = (Et + 255) / 256;
    int nWB = (N + 7) / 8;
    int mmB = (N + 63) / 64;

    // fork: side stream runs first matmul, then the big zeroing kernel
    cudaEventRecord(evFork, 0);
    cudaStreamWaitEvent(s1, evFork, 0);
    k_matmul<<<mmB, 256, 0, s1>>>(x, W0, p_h, N);
    cudaEventRecord(evJoin, s1);
    k_zero<<<456, 256, 0, s1>>>(N, out + KSEL * F);
    cudaEventRecord(evZero, s1);

    // main stream: CSR build
    k_count<<<eB, 256>>>(ei, E, linW, linb, attW);
    k_scan<<<1, 1024>>>(N);
    k_scatter<<<tEB, 256>>>(ei, E, N);

    // join 1: gcnagg needs matmul output
    cudaStreamWaitEvent(0, evJoin, 0);

    k_gcnagg<false><<<nWB, 256>>>(p_h, b0, nullptr, p_x1, N);
    k_matmul<<<mmB, 256>>>(p_x1, W1, p_h, N);
    k_gcnagg<true><<<nWB, 256>>>(p_h, b1, attW, p_x2, N);

    k_attn<<<nWB, 256>>>(p_x2, attb, N);
    k_xc<<<nWB, 256>>>(le1W, le1b, le2W, le3W, N);
    k_fitness<<<nWB, 256>>>(le3b, N);

    int nb1 = (N + 2047) / 2048;
    k_topk1<<<nb1, 1024>>>(N);
    k_topk2<<<1, 1024>>>(nb1 * 256);

    // join 2: entries needs g_AS / outA zeroed
    cudaStreamWaitEvent(0, evZero, 0);

    k_entries<<<(KSEL * 32 + 255) / 256, 256>>>();
    k_Anew_final<<<512, 256>>>(out);

    (void)n_in; (void)out_size;
}

// round 17
// speedup vs baseline: 1.0346x; 1.0346x over previous
#include <cuda_runtime.h>
#include <math.h>

#define F 64
#define KSEL 256
#define NMAX 20000
#define EMAX 320000
#define ETMAX (NMAX + EMAX)
#define NEG_INF (-3.402823466e38f)
#define XS 68

// ---------------- scratch (static __device__, zero-initialized) ----------------
__device__ float g_h[NMAX * F];
__device__ float g_x1[NMAX * F];
__device__ float g_x2[NMAX * F];
__device__ float g_xc[NMAX * F];
__device__ float g_dis[NMAX];
__device__ float g_pa[NMAX];
__device__ float g_av[NMAX], g_bv[NMAX], g_cv[NMAX], g_fit[NMAX];
__device__ float g_score[ETMAX];
__device__ int   g_rowS[ETMAX];
__device__ int   g_epos[EMAX];
__device__ int   g_cnt[NMAX], g_ptr[NMAX + 1];
__device__ unsigned long long g_cand[16 * 256];
__device__ int   g_perm[KSEL];
__device__ float g_fitk[KSEL];
__device__ int   g_entR[ETMAX], g_entK[ETMAX];
__device__ float g_entV[ETMAX];
__device__ int   g_nent;
__device__ float g_vq[F + 1];
__device__ float g_AS[(size_t)NMAX * KSEL];

// ---------------- helpers ----------------
__device__ __forceinline__ float wredsum(float v) {
    #pragma unroll
    for (int d = 16; d; d >>= 1) v += __shfl_xor_sync(0xFFFFFFFFu, v, d);
    return v;
}
__device__ __forceinline__ float wredmax(float v) {
    #pragma unroll
    for (int d = 16; d; d >>= 1) v = fmaxf(v, __shfl_xor_sync(0xFFFFFFFFu, v, d));
    return v;
}
__device__ __forceinline__ unsigned long long make_key(float f, int i) {
    unsigned u = __float_as_uint(f);
    u = (u & 0x80000000u) ? ~u : (u | 0x80000000u);
    return ((unsigned long long)u << 32) | (unsigned)(0xFFFFFFFFu - (unsigned)i);
}
template <int NSORT>
__device__ void bitonic_desc(unsigned long long* s) {
    int t = threadIdx.x;
    for (int k = 2; k <= NSORT; k <<= 1) {
        for (int j = k >> 1; j > 0; j >>= 1) {
            for (int i = t; i < NSORT; i += blockDim.x) {
                int ixj = i ^ j;
                if (ixj > i) {
                    unsigned long long a = s[i], b = s[ixj];
                    bool sw = ((i & k) == 0) ? (a < b) : (a > b);
                    if (sw) { s[i] = b; s[ixj] = a; }
                }
            }
            __syncthreads();
        }
    }
}

// ---------------- CSR build (zeroes g_AS/outA inside, computes vq) -----------
__global__ void k_count(const int* __restrict__ ei, int E, int Nn,
                        const float* __restrict__ linW, const float* __restrict__ linb,
                        const float* __restrict__ attW, float* __restrict__ outA) {
    int e = blockIdx.x * blockDim.x + threadIdx.x;
    int gsz = gridDim.x * blockDim.x;
    float4 z4 = make_float4(0.f, 0.f, 0.f, 0.f);
    size_t nAS4 = ((size_t)Nn * KSEL) >> 2;
    float4* AS4 = (float4*)g_AS;
    for (size_t i = e; i < nAS4; i += gsz) AS4[i] = z4;
    float4* outA4 = (float4*)outA;
    for (int i = e; i < (KSEL * KSEL) / 4; i += gsz) outA4[i] = z4;
    if (blockIdx.x == 0) {
        int t = threadIdx.x;
        if (t < F) {
            float s = 0.f;
            #pragma unroll 8
            for (int c = 0; c < F; c++) s += linW[t * F + c] * attW[c];
            g_vq[t] = s;
        } else if (t == F) {
            float s = 0.f;
            for (int c = 0; c < F; c++) s += linb[c] * attW[c];
            g_vq[F] = s;
        } else if (t == F + 1) {
            g_nent = 0;
        }
    }
    if (e >= E) return;
    int c = ei[E + e];
    g_epos[e] = atomicAdd(&g_cnt[c], 1);
}

// scan: 2 elements/thread/iter (10 iterations for N=20000)
__global__ void __launch_bounds__(1024) k_scan(int Nn) {
    __shared__ int warpsum[32];
    int t = threadIdx.x, lane = t & 31, wid = t >> 5;
    int offset = 0;
    for (int base = 0; base < Nn; base += 2048) {
        int i0 = base + 2 * t;
        int v0 = 0, v1 = 0;
        if (i0 < Nn)     { v0 = g_cnt[i0] + 1;     g_cnt[i0] = 0; }
        if (i0 + 1 < Nn) { v1 = g_cnt[i0 + 1] + 1; g_cnt[i0 + 1] = 0; }
        int pair = v0 + v1;
        int x = pair;
        #pragma unroll
        for (int d = 1; d < 32; d <<= 1) {
            int y = __shfl_up_sync(0xFFFFFFFFu, x, d);
            if (lane >= d) x += y;
        }
        if (lane == 31) warpsum[wid] = x;
        __syncthreads();
        if (wid == 0) {
            int s = warpsum[lane];
            #pragma unroll
            for (int d = 1; d < 32; d <<= 1) {
                int y = __shfl_up_sync(0xFFFFFFFFu, s, d);
                if (lane >= d) s += y;
            }
            warpsum[lane] = s;
        }
        __syncthreads();
        int ex = x - pair + (wid > 0 ? warpsum[wid - 1] : 0);
        int val0 = offset + ex;
        if (i0 < Nn) {
            g_ptr[i0] = val0;
            g_dis[i0] = rsqrtf((float)v0);
        }
        if (i0 + 1 < Nn) {
            g_ptr[i0 + 1] = val0 + v0;
            g_dis[i0 + 1] = rsqrtf((float)v1);
        }
        offset += warpsum[31];
        __syncthreads();
    }
    if (t == 0) g_ptr[Nn] = offset;
}

__global__ void k_scatter(const int* __restrict__ ei, int E, int Nn) {
    int e = blockIdx.x * blockDim.x + threadIdx.x;
    int Et = E + Nn;
    if (e >= Et) return;
    if (e < E) {
        int c = ei[E + e];
        g_rowS[g_ptr[c] + g_epos[e]] = ei[e];
    } else {
        int c = e - E;
        g_rowS[g_ptr[c + 1] - 1] = c;
    }
}

// ---------------- dense matmul ----------------
__global__ void __launch_bounds__(256) k_matmul(const float* __restrict__ X,
                                                const float* __restrict__ W,
                                                float* __restrict__ Y, int n) {
    __shared__ float Ws[F * F];
    __shared__ float Xs[64 * XS];
    int t = threadIdx.x;
    const float4* W4 = (const float4*)W;
    float4* Ws4 = (float4*)Ws;
    #pragma unroll
    for (int i = 0; i < 4; i++) Ws4[t + 256 * i] = W4[t + 256 * i];

    int r0 = blockIdx.x * 64;
    int rows = n - r0; if (rows > 64) rows = 64;
    const float4* X4 = (const float4*)(X + (size_t)r0 * F);
    for (int i = t; i < 64 * 16; i += 256) {
        int row = i >> 4, c4 = i & 15;
        float4 v = (row < rows) ? X4[row * 16 + c4] : make_float4(0.f, 0.f, 0.f, 0.f);
        *(float4*)(Xs + row * XS + c4 * 4) = v;
    }
    __syncthreads();

    int tx = t & 15, ty = t >> 4;
    float4 a0 = make_float4(0.f,0.f,0.f,0.f), a1 = a0, a2 = a0, a3 = a0;
    const float* xr0 = Xs + (ty * 4 + 0) * XS;
    const float* xr1 = Xs + (ty * 4 + 1) * XS;
    const float* xr2 = Xs + (ty * 4 + 2) * XS;
    const float* xr3 = Xs + (ty * 4 + 3) * XS;
    #pragma unroll
    for (int k0 = 0; k0 < F; k0 += 4) {
        float4 xv0 = *(const float4*)(xr0 + k0);
        float4 xv1 = *(const float4*)(xr1 + k0);
        float4 xv2 = *(const float4*)(xr2 + k0);
        float4 xv3 = *(const float4*)(xr3 + k0);
        #pragma unroll
        for (int kk = 0; kk < 4; kk++) {
            float4 wv = *(const float4*)(Ws + (k0 + kk) * F + tx * 4);
            float x0 = (&xv0.x)[kk], x1 = (&xv1.x)[kk];
            float x2 = (&xv2.x)[kk], x3 = (&xv3.x)[kk];
            a0.x += x0 * wv.x; a0.y += x0 * wv.y; a0.z += x0 * wv.z; a0.w += x0 * wv.w;
            a1.x += x1 * wv.x; a1.y += x1 * wv.y; a1.z += x1 * wv.z; a1.w += x1 * wv.w;
            a2.x += x2 * wv.x; a2.y += x2 * wv.y; a2.z += x2 * wv.z; a2.w += x2 * wv.w;
            a3.x += x3 * wv.x; a3.y += x3 * wv.y; a3.z += x3 * wv.z; a3.w += x3 * wv.w;
        }
    }
    int rb = r0 + ty * 4;
    if (rb + 0 < n) ((float4*)(Y + (size_t)(rb + 0) * F))[tx] = a0;
    if (rb + 1 < n) ((float4*)(Y + (size_t)(rb + 1) * F))[tx] = a1;
    if (rb + 2 < n) ((float4*)(Y + (size_t)(rb + 2) * F))[tx] = a2;
    if (rb + 3 < n) ((float4*)(Y + (size_t)(rb + 3) * F))[tx] = a3;
}

// ---------------- segment gathers ----------------
template <bool WITH_PA>
__global__ void k_gcnagg(const float* __restrict__ h, const float* __restrict__ b,
                         const float* __restrict__ attW, float* __restrict__ out, int n) {
    int w = (blockIdx.x * blockDim.x + threadIdx.x) >> 5;
    int l = threadIdx.x & 31;
    if (w >= n) return;
    int half = l >> 4, f4 = l & 15;
    int s = g_ptr[w], e = g_ptr[w + 1];
    float dc = g_dis[w];
    float4 a0 = make_float4(0.f, 0.f, 0.f, 0.f);
    float4 a1 = make_float4(0.f, 0.f, 0.f, 0.f);
    int p = s + half;
    for (; p + 2 < e; p += 4) {
        int r0 = g_rowS[p], r1 = g_rowS[p + 2];
        float n0 = dc * g_dis[r0], n1 = dc * g_dis[r1];
        float4 h0 = *(const float4*)(h + r0 * F + f4 * 4);
        float4 h1 = *(const float4*)(h + r1 * F + f4 * 4);
        a0.x += n0 * h0.x; a0.y += n0 * h0.y; a0.z += n0 * h0.z; a0.w += n0 * h0.w;
        a1.x += n1 * h1.x; a1.y += n1 * h1.y; a1.z += n1 * h1.z; a1.w += n1 * h1.w;
    }
    if (p < e) {
        int r0 = g_rowS[p];
        float n0 = dc * g_dis[r0];
        float4 h0 = *(const float4*)(h + r0 * F + f4 * 4);
        a0.x += n0 * h0.x; a0.y += n0 * h0.y; a0.z += n0 * h0.z; a0.w += n0 * h0.w;
    }
    a0.x += a1.x; a0.y += a1.y; a0.z += a1.z; a0.w += a1.w;
    a0.x += __shfl_xor_sync(0xFFFFFFFFu, a0.x, 16);
    a0.y += __shfl_xor_sync(0xFFFFFFFFu, a0.y, 16);
    a0.z += __shfl_xor_sync(0xFFFFFFFFu, a0.z, 16);
    a0.w += __shfl_xor_sync(0xFFFFFFFFu, a0.w, 16);
    float4 bb = *(const float4*)(b + f4 * 4);
    a0.x = fmaxf(a0.x + bb.x, 0.f);
    a0.y = fmaxf(a0.y + bb.y, 0.f);
    a0.z = fmaxf(a0.z + bb.z, 0.f);
    a0.w = fmaxf(a0.w + bb.w, 0.f);
    if (half == 0) *(float4*)(out + w * F + f4 * 4) = a0;
    if (WITH_PA) {
        float part = 0.f;
        if (half == 0) {
            float4 aw = *(const float4*)(attW + F + f4 * 4);
            part = a0.x * aw.x + a0.y * aw.y + a0.z * aw.z + a0.w * aw.w;
        }
        part = wredsum(part);
        if (l == 0) g_pa[w] = part;
    }
}

// fused: segmax over x2 -> qa in registers -> leaky score -> softmax
__global__ void k_attn(const float* __restrict__ x2, const float* __restrict__ attb, int n) {
    int w = (blockIdx.x * blockDim.x + threadIdx.x) >> 5;
    int l = threadIdx.x & 31;
    if (w >= n) return;
    int half = l >> 4, f4 = l & 15;
    int s = g_ptr[w], e = g_ptr[w + 1];
    float4 a0 = make_float4(NEG_INF, NEG_INF, NEG_INF, NEG_INF);
    float4 a1 = make_float4(NEG_INF, NEG_INF, NEG_INF, NEG_INF);
    int p = s + half;
    for (; p + 2 < e; p += 4) {
        int r0 = g_rowS[p], r1 = g_rowS[p + 2];
        float4 h0 = *(const float4*)(x2 + r0 * F + f4 * 4);
        float4 h1 = *(const float4*)(x2 + r1 * F + f4 * 4);
        a0.x = fmaxf(a0.x, h0.x); a0.y = fmaxf(a0.y, h0.y);
        a0.z = fmaxf(a0.z, h0.z); a0.w = fmaxf(a0.w, h0.w);
        a1.x = fmaxf(a1.x, h1.x); a1.y = fmaxf(a1.y, h1.y);
        a1.z = fmaxf(a1.z, h1.z); a1.w = fmaxf(a1.w, h1.w);
    }
    if (p < e) {
        int r0 = g_rowS[p];
        float4 h0 = *(const float4*)(x2 + r0 * F + f4 * 4);
        a0.x = fmaxf(a0.x, h0.x); a0.y = fmaxf(a0.y, h0.y);
        a0.z = fmaxf(a0.z, h0.z); a0.w = fmaxf(a0.w, h0.w);
    }
    a0.x = fmaxf(a0.x, a1.x); a0.y = fmaxf(a0.y, a1.y);
    a0.z = fmaxf(a0.z, a1.z); a0.w = fmaxf(a0.w, a1.w);
    a0.x = fmaxf(a0.x, __shfl_xor_sync(0xFFFFFFFFu, a0.x, 16));
    a0.y = fmaxf(a0.y, __shfl_xor_sync(0xFFFFFFFFu, a0.y, 16));
    a0.z = fmaxf(a0.z, __shfl_xor_sync(0xFFFFFFFFu, a0.z, 16));
    a0.w = fmaxf(a0.w, __shfl_xor_sync(0xFFFFFFFFu, a0.w, 16));
    float part = 0.f;
    if (half == 0) {
        float4 vv = *(const float4*)(g_vq + f4 * 4);
        part = a0.x * vv.x + a0.y * vv.y + a0.z * vv.z + a0.w * vv.w;
    }
    part = wredsum(part);
    float qb = part + g_vq[F] + attb[0];
    int deg = e - s;
    if (deg <= 32) {
        int q = s + l;
        bool act = q < e;
        float sc = NEG_INF;
        if (act) {
            sc = qb + g_pa[g_rowS[q]];
            sc = (sc >= 0.f) ? sc : 0.2f * sc;
        }
        float m = wredmax(sc);
        float ex = act ? expf(sc - m) : 0.f;
        float sum = wredsum(ex);
        if (act) g_score[q] = ex / sum;
    } else {
        float m = NEG_INF;
        for (int q = s + l; q < e; q += 32) {
            float sc = qb + g_pa[g_rowS[q]];
            sc = (sc >= 0.f) ? sc : 0.2f * sc;
            g_score[q] = sc;
            m = fmaxf(m, sc);
        }
        m = wredmax(m);
        float sum = 0.f;
        for (int q = s + l; q < e; q += 32) sum += expf(g_score[q] - m);
        sum = wredsum(sum);
        float invs = 1.f / sum;
        for (int q = s + l; q < e; q += 32) g_score[q] = expf(g_score[q] - m) * invs;
    }
}

// xc = sum score * x2[row], fused le dots epilogue
__global__ void k_xc(const float* __restrict__ le1W, const float* __restrict__ le1b,
                     const float* __restrict__ le2W, const float* __restrict__ le3W, int n) {
    int w = (blockIdx.x * blockDim.x + threadIdx.x) >> 5;
    int l = threadIdx.x & 31;
    if (w >= n) return;
    int half = l >> 4, f4 = l & 15;
    int s = g_ptr[w], e = g_ptr[w + 1];
    float4 a0 = make_float4(0.f, 0.f, 0.f, 0.f);
    float4 a1 = make_float4(0.f, 0.f, 0.f, 0.f);
    int p = s + half;
    for (; p + 2 < e; p += 4) {
        int r0 = g_rowS[p], r1 = g_rowS[p + 2];
        float s0 = g_score[p], s1 = g_score[p + 2];
        float4 h0 = *(const float4*)(g_x2 + r0 * F + f4 * 4);
        float4 h1 = *(const float4*)(g_x2 + r1 * F + f4 * 4);
        a0.x += s0 * h0.x; a0.y += s0 * h0.y; a0.z += s0 * h0.z; a0.w += s0 * h0.w;
        a1.x += s1 * h1.x; a1.y += s1 * h1.y; a1.z += s1 * h1.z; a1.w += s1 * h1.w;
    }
    if (p < e) {
        int r0 = g_rowS[p];
        float s0 = g_score[p];
        float4 h0 = *(const float4*)(g_x2 + r0 * F + f4 * 4);
        a0.x += s0 * h0.x; a0.y += s0 * h0.y; a0.z += s0 * h0.z; a0.w += s0 * h0.w;
    }
    a0.x += a1.x; a0.y += a1.y; a0.z += a1.z; a0.w += a1.w;
    a0.x += __shfl_xor_sync(0xFFFFFFFFu, a0.x, 16);
    a0.y += __shfl_xor_sync(0xFFFFFFFFu, a0.y, 16);
    a0.z += __shfl_xor_sync(0xFFFFFFFFu, a0.z, 16);
    a0.w += __shfl_xor_sync(0xFFFFFFFFu, a0.w, 16);
    float s1 = 0.f, s2 = 0.f, s3 = 0.f;
    if (half == 0) {
        *(float4*)(g_xc + w * F + f4 * 4) = a0;
        float4 w1 = *(const float4*)(le1W + f4 * 4);
        float4 w2 = *(const float4*)(le2W + f4 * 4);
        float4 w3 = *(const float4*)(le3W + f4 * 4);
        s1 = a0.x * w1.x + a0.y * w1.y + a0.z * w1.z + a0.w * w1.w;
        s2 = a0.x * w2.x + a0.y * w2.y + a0.z * w2.z + a0.w * w2.w;
        s3 = a0.x * w3.x + a0.y * w3.y + a0.z * w3.z + a0.w * w3.w;
    }
    s1 = wredsum(s1); s2 = wredsum(s2); s3 = wredsum(s3);
    if (l == 0) { g_av[w] = s1 + le1b[0]; g_bv[w] = s2; g_cv[w] = s3; }
}

__global__ void k_fitness(const float* __restrict__ le3b, int n) {
    int w = (blockIdx.x * blockDim.x + threadIdx.x) >> 5;
    int l = threadIdx.x & 31;
    if (w >= n) return;
    int s = g_ptr[w], e = g_ptr[w + 1];
    float sum = 0.f;
    for (int p = s + l; p < e; p += 32) sum += g_av[g_rowS[p]];
    sum = wredsum(sum);
    if (l == 0) {
        float deg = (float)(e - s);
        float val = sum - deg * g_bv[w] + g_cv[w] + le3b[0];
        g_fit[w] = 1.f / (1.f + expf(-val));
    }
}

// ---------------- exact top-K (jax semantics) ----------------
__global__ void __launch_bounds__(1024) k_topk1(int n) {
    __shared__ unsigned long long s[2048];
    int t = threadIdx.x;
    int base = blockIdx.x * 2048;
    for (int j = t; j < 2048; j += 1024) {
        int i = base + j;
        s[j] = (i < n) ? make_key(g_fit[i], i) : 0ULL;
    }
    __syncthreads();
    bitonic_desc<2048>(s);
    if (t < 256) g_cand[blockIdx.x * 256 + t] = s[t];
}

__global__ void __launch_bounds__(1024) k_topk2(int n2) {
    __shared__ unsigned long long s[4096];
    int t = threadIdx.x;
    for (int j = t; j < 4096; j += 1024) s[j] = (j < n2) ? g_cand[j] : 0ULL;
    __syncthreads();
    bitonic_desc<4096>(s);
    if (t < KSEL) {
        unsigned long long key = s[t];
        int idx = (int)(0xFFFFFFFFu - (unsigned)(key & 0xFFFFFFFFu));
        g_perm[t] = idx;
        g_fitk[t] = g_fit[idx];
    }
}

// ---------------- sparse S entries + AS scatter (perm-driven, warp per k) ----
__global__ void k_entries() {
    int k = (blockIdx.x * blockDim.x + threadIdx.x) >> 5;
    int l = threadIdx.x & 31;
    if (k >= KSEL) return;
    int node = g_perm[k];
    int s = g_ptr[node], e = g_ptr[node + 1];
    for (int p = s + l; p < e; p += 32) {
        int r = g_rowS[p];
        float val = g_score[p];
        int idx = atomicAdd(&g_nent, 1);
        g_entR[idx] = r;
        g_entK[idx] = k;
        g_entV[idx] = val;
        int s2 = g_ptr[r], e2 = g_ptr[r + 1];
        for (int q = s2; q < e2; q++)
            atomicAdd(&g_AS[(size_t)g_rowS[q] * KSEL + k], val);
    }
}

// A_new (skipping diagonal contributions) fused with final outputs.
__global__ void k_Anew_final(float* __restrict__ out) {
    float* outA = out + KSEL * F;
    int gtid = blockIdx.x * blockDim.x + threadIdx.x;
    int gsz = gridDim.x * blockDim.x;
    int w = gtid >> 5;
    int l = threadIdx.x & 31;
    int nw = gsz >> 5;
    int ne = g_nent;
    for (int i = w; i < ne; i += nw) {
        int r = g_entR[i];
        int k1 = g_entK[i];
        float v = g_entV[i];
        const float4* asr = (const float4*)(g_AS + (size_t)r * KSEL);
        float4 x0 = asr[l * 2], x1 = asr[l * 2 + 1];
        float* dst = outA + k1 * KSEL + l * 8;
        int c0 = l * 8;
        if (c0 + 0 != k1) atomicAdd(dst + 0, v * x0.x);
        if (c0 + 1 != k1) atomicAdd(dst + 1, v * x0.y);
        if (c0 + 2 != k1) atomicAdd(dst + 2, v * x0.z);
        if (c0 + 3 != k1) atomicAdd(dst + 3, v * x0.w);
        if (c0 + 4 != k1) atomicAdd(dst + 4, v * x1.x);
        if (c0 + 5 != k1) atomicAdd(dst + 5, v * x1.y);
        if (c0 + 6 != k1) atomicAdd(dst + 6, v * x1.z);
        if (c0 + 7 != k1) atomicAdd(dst + 7, v * x1.w);
    }
    for (int i = gtid; i < KSEL * F; i += gsz) {
        int k = i >> 6, f = i & 63;
        out[i] = g_xc[g_perm[k] * F + f] * g_fitk[k];
    }
    for (int i = gtid; i < KSEL; i += gsz) {
        out[KSEL * F + KSEL * KSEL + i] = (float)g_perm[i];
        out[KSEL * F + i * KSEL + i] = 1.0f;
    }
}

// ---------------- launch ----------------
extern "C" void kernel_launch(void* const* d_in, const int* in_sizes, int n_in,
                              void* d_out, int out_size) {
    const float* x     = (const float*)d_in[0];
    const int*   ei    = (const int*)d_in[1];
    const float* W0    = (const float*)d_in[2];
    const float* b0    = (const float*)d_in[3];
    const float* W1    = (const float*)d_in[4];
    const float* b1    = (const float*)d_in[5];
    const float* linW  = (const float*)d_in[6];
    const float* linb  = (const float*)d_in[7];
    const float* attW  = (const float*)d_in[8];
    const float* attb  = (const float*)d_in[9];
    const float* le1W  = (const float*)d_in[10];
    const float* le1b  = (const float*)d_in[11];
    const float* le2W  = (const float*)d_in[12];
    const float* le3W  = (const float*)d_in[13];
    const float* le3b  = (const float*)d_in[14];
    float* out = (float*)d_out;

    int N  = in_sizes[0] / F;
    int E  = in_sizes[1] / 2;
    int Et = E + N;

    void* vp;
    cudaGetSymbolAddress(&vp, g_h);   float* p_h  = (float*)vp;
    cudaGetSymbolAddress(&vp, g_x1);  float* p_x1 = (float*)vp;
    cudaGetSymbolAddress(&vp, g_x2);  float* p_x2 = (float*)vp;

    static cudaStream_t s1 = nullptr;
    static cudaEvent_t evFork = nullptr, evJoin = nullptr;
    if (!s1) {
        cudaStreamCreateWithFlags(&s1, cudaStreamNonBlocking);
        cudaEventCreateWithFlags(&evFork, cudaEventDisableTiming);
        cudaEventCreateWithFlags(&evJoin, cudaEventDisableTiming);
    }

    int eB  = (E + 255) / 256;
    int tEB = (Et + 255) / 256;
    int nWB = (N + 7) / 8;
    int mmB = (N + 63) / 64;

    // fork: side stream runs first matmul (kernel only)
    cudaEventRecord(evFork, 0);
    cudaStreamWaitEvent(s1, evFork, 0);
    k_matmul<<<mmB, 256, 0, s1>>>(x, W0, p_h, N);
    cudaEventRecord(evJoin, s1);

    // main stream: CSR build (+zeroing, vq, nent reset inside k_count)
    k_count<<<eB, 256>>>(ei, E, N, linW, linb, attW, out + KSEL * F);
    k_scan<<<1, 1024>>>(N);
    k_scatter<<<tEB, 256>>>(ei, E, N);

    // join: gcnagg needs both CSR and matmul output
    cudaStreamWaitEvent(0, evJoin, 0);

    k_gcnagg<false><<<nWB, 256>>>(p_h, b0, nullptr, p_x1, N);
    k_matmul<<<mmB, 256>>>(p_x1, W1, p_h, N);
    k_gcnagg<true><<<nWB, 256>>>(p_h, b1, attW, p_x2, N);

    k_attn<<<nWB, 256>>>(p_x2, attb, N);
    k_xc<<<nWB, 256>>>(le1W, le1b, le2W, le3W, N);
    k_fitness<<<nWB, 256>>>(le3b, N);

    int nb1 = (N + 2047) / 2048;
    k_topk1<<<nb1, 1024>>>(N);
    k_topk2<<<1, 1024>>>(nb1 * 256);

    k_entries<<<(KSEL * 32 + 255) / 256, 256>>>();
    k_Anew_final<<<512, 256>>>(out);

    (void)n_in; (void)out_size;
}